// round 8
// baseline (speedup 1.0000x reference)
#include <cuda_runtime.h>
#include <cuda_fp16.h>
#include <cuda_bf16.h>
#include <cstdint>

#define N_NODES 100000
#define N_EDGES 1600000
#define D 64

// ---------------- static device scratch (no allocation allowed) -------------
__device__ int    g_deg[N_NODES];       // in-degree (without self loop)
__device__ float  g_dinv[N_NODES];      // rsqrt(deg+1)
__device__ int    g_off[N_NODES];       // compact CSR offsets
__device__ int    g_cnt[N_NODES];       // fill cursors
__device__ int    g_src[N_EDGES];       // compact CSR-by-dst (6.4MB, L2-friendly)
__device__ __half g_h[(size_t)N_NODES * D];   // layer-1 prescaled features (fp16)
__device__ __half g_h2[(size_t)N_NODES * D];  // layer-2 prescaled features (fp16)
__device__ int    g_cursor;

// ---------------- f32x2 packed-math helpers (Blackwell) ---------------------
__device__ __forceinline__ unsigned long long pack2(float lo, float hi) {
    unsigned long long r;
    asm("mov.b64 %0, {%1, %2};" : "=l"(r)
        : "r"(__float_as_uint(lo)), "r"(__float_as_uint(hi)));
    return r;
}
__device__ __forceinline__ unsigned long long fma2(unsigned long long a,
                                                   unsigned long long b,
                                                   unsigned long long c) {
    unsigned long long d;
    asm("fma.rn.f32x2 %0, %1, %2, %3;" : "=l"(d) : "l"(a), "l"(b), "l"(c));
    return d;
}
__device__ __forceinline__ unsigned long long mul2(unsigned long long a,
                                                   unsigned long long b) {
    unsigned long long d;
    asm("mul.rn.f32x2 %0, %1, %2;" : "=l"(d) : "l"(a), "l"(b));
    return d;
}
__device__ __forceinline__ float2 unpack2(unsigned long long v) {
    float2 f;
    unsigned lo, hi;
    asm("mov.b64 {%0, %1}, %2;" : "=r"(lo), "=r"(hi) : "l"(v));
    f.x = __uint_as_float(lo); f.y = __uint_as_float(hi);
    return f;
}

// ---------------------------------------------------------------------------
__global__ void init_kernel() {
    int i = blockIdx.x * blockDim.x + threadIdx.x;
    if (i == 0) g_cursor = 0;
    if (i < N_NODES) g_deg[i] = 0;
}

// 4 edges per thread, vectorized load, no-return atomics.
__global__ void deg_kernel(const int* __restrict__ ei) {
    int e4 = blockIdx.x * blockDim.x + threadIdx.x;
    if (e4 * 4 < N_EDGES) {
        int4 d4 = *(const int4*)(ei + N_EDGES + e4 * 4);
        atomicAdd(&g_deg[d4.x], 1);
        atomicAdd(&g_deg[d4.y], 1);
        atomicAdd(&g_deg[d4.z], 1);
        atomicAdd(&g_deg[d4.w], 1);
    }
}

// Reserve contiguous CSR ranges via warp-aggregated atomic; compute dinv; zero cnt.
__global__ void offsets_kernel() {
    int n = blockIdx.x * blockDim.x + threadIdx.x;
    int d = (n < N_NODES) ? g_deg[n] : 0;
    int lane = threadIdx.x & 31;
    int incl = d;
    #pragma unroll
    for (int o = 1; o < 32; o <<= 1) {
        int v = __shfl_up_sync(0xFFFFFFFFu, incl, o);
        if (lane >= o) incl += v;
    }
    int total = __shfl_sync(0xFFFFFFFFu, incl, 31);
    int base = 0;
    if (lane == 31) base = atomicAdd(&g_cursor, total);
    base = __shfl_sync(0xFFFFFFFFu, base, 31);
    if (n < N_NODES) {
        g_off[n]  = base + (incl - d);
        g_cnt[n]  = 0;
        g_dinv[n] = rsqrtf((float)(d + 1));
    }
}

// Minimal compact binning: one atomic + one 4B store per edge. 2 edges/thread.
__global__ void bin_kernel(const int* __restrict__ ei) {
    int e2 = blockIdx.x * blockDim.x + threadIdx.x;
    if (e2 * 2 < N_EDGES) {
        int2 s2 = *(const int2*)(ei + e2 * 2);
        int2 d2 = *(const int2*)(ei + N_EDGES + e2 * 2);
        int p0 = g_off[d2.x] + atomicAdd(&g_cnt[d2.x], 1);
        g_src[p0] = s2.x;
        int p1 = g_off[d2.y] + atomicAdd(&g_cnt[d2.y], 1);
        g_src[p1] = s2.y;
    }
}

// g_h[row] = half( dinv[row] * (x[row] @ W1) ) — prescaled. Needs dinv only
// (not the CSR), so it can overlap with bin_kernel on another stream.
__global__ void gemm1_kernel(const float* __restrict__ A,
                             const float* __restrict__ W) {
    __shared__ float4 sW[1024];          // 64 x 16 float4
    int t = threadIdx.x;
    const float4* Wv = (const float4*)W;
    #pragma unroll
    for (int r = 0; r < 4; r++) sW[t + 256 * r] = Wv[t + 256 * r];
    __syncthreads();

    int row = blockIdx.x * 256 + t;
    if (row >= N_NODES) return;

    const float4* Av = (const float4*)(A + (size_t)row * D);
    unsigned long long acc[32];
    #pragma unroll
    for (int j = 0; j < 32; j++) acc[j] = 0ull;

    #pragma unroll
    for (int kk = 0; kk < 4; kk++) {
        float4 a4[4];
        #pragma unroll
        for (int i = 0; i < 4; i++) a4[i] = Av[kk * 4 + i];
        #pragma unroll
        for (int ki = 0; ki < 16; ki++) {
            float av = ((const float*)a4)[ki];
            unsigned long long ap = pack2(av, av);
            int k = kk * 16 + ki;
            #pragma unroll
            for (int j = 0; j < 16; j++) {
                union { float4 f; unsigned long long u[2]; } w;
                w.f = sW[k * 16 + j];
                acc[j * 2 + 0] = fma2(ap, w.u[0], acc[j * 2 + 0]);
                acc[j * 2 + 1] = fma2(ap, w.u[1], acc[j * 2 + 1]);
            }
        }
    }
    float dinv = g_dinv[row];
    unsigned long long dp = pack2(dinv, dinv);
    uint4* Cv = (uint4*)(g_h + (size_t)row * D);
    #pragma unroll
    for (int j = 0; j < 8; j++) {
        union { uint4 v; __half2 h2[8]; } o;
        #pragma unroll
        for (int q = 0; q < 4; q++)
            o.h2[q] = __float22half2_rn(unpack2(mul2(acc[j * 4 + q], pack2(1.f,1.f))));
        // note: scale applied below per pair to keep one mul2 per accumulator
        #pragma unroll
        for (int q = 0; q < 4; q++)
            o.h2[q] = __float22half2_rn(unpack2(mul2(acc[j * 4 + q], dp)));
        Cv[j] = o.v;
    }
}

// Aggregate 8 columns of node n from prescaled buffer hs: acc = hs_n + sum hs_src.
__device__ __forceinline__ void aggregate8(const __half* __restrict__ hs,
                                           int n, int c, float2 acc[4]) {
    union { uint4 v; __half2 h2[4]; } u;
    u.v = *(const uint4*)(hs + (size_t)n * D + c);       // self term (prescaled)
    #pragma unroll
    for (int j = 0; j < 4; j++) acc[j] = __half22float2(u.h2[j]);

    int s0  = g_off[n];
    int cnt = g_deg[n];
    const int* lst = g_src + s0;
    #pragma unroll 4
    for (int i = 0; i < cnt; i++) {
        int s = lst[i];
        union { uint4 v; __half2 h2[4]; } w;
        w.v = *(const uint4*)(hs + (size_t)s * D + c);   // 128B row gather
        #pragma unroll
        for (int j = 0; j < 4; j++) {
            float2 f = __half22float2(w.h2[j]);
            acc[j].x += f.x; acc[j].y += f.y;
        }
    }
}

// Fused: t_row = relu(dinv*agg(g_h) + b1) in smem; then g_h2 = half(dinv * (t_row @ W2)).
// Output buffer is g_h2 (g_h is still being read by other blocks).
// 256 threads = 32 nodes x 8 threads; 3125 blocks cover N exactly.
__global__ void fused_agg_gemm_kernel(const float* __restrict__ b1,
                                      const float* __restrict__ W2) {
    __shared__ float  sRows[32 * D];     // 8KB aggregated activations
    __shared__ float4 sW2[1024];         // 16KB W2

    int t = threadIdx.x;
    const float4* Wv = (const float4*)W2;
    #pragma unroll
    for (int r = 0; r < 4; r++) sW2[t + 256 * r] = Wv[t + 256 * r];

    int nl = t >> 3;                     // node within block
    int n  = blockIdx.x * 32 + nl;
    int c  = (t & 7) * 8;

    float2 acc[4];
    aggregate8((const __half*)g_h, n, c, acc);

    float dn = g_dinv[n];
    float4 b0 = *(const float4*)(b1 + c);
    float4 bb = *(const float4*)(b1 + c + 4);
    float* rowp = &sRows[nl * D + c];
    rowp[0] = fmaxf(fmaf(dn, acc[0].x, b0.x), 0.f);
    rowp[1] = fmaxf(fmaf(dn, acc[0].y, b0.y), 0.f);
    rowp[2] = fmaxf(fmaf(dn, acc[1].x, b0.z), 0.f);
    rowp[3] = fmaxf(fmaf(dn, acc[1].y, b0.w), 0.f);
    rowp[4] = fmaxf(fmaf(dn, acc[2].x, bb.x), 0.f);
    rowp[5] = fmaxf(fmaf(dn, acc[2].y, bb.y), 0.f);
    rowp[6] = fmaxf(fmaf(dn, acc[3].x, bb.z), 0.f);
    rowp[7] = fmaxf(fmaf(dn, acc[3].y, bb.w), 0.f);
    __syncthreads();

    // phase 2: 8 output columns (c..c+7) of g_h2[n] = dinv[n] * (row @ W2)
    const float* row = &sRows[nl * D];
    unsigned long long acc2[4] = {0ull, 0ull, 0ull, 0ull};
    int j0 = (t & 7) * 2;
    #pragma unroll 16
    for (int k = 0; k < D; k++) {
        float a = row[k];
        unsigned long long ap = pack2(a, a);
        union { float4 f; unsigned long long u[2]; } w0, w1;
        w0.f = sW2[k * 16 + j0];
        w1.f = sW2[k * 16 + j0 + 1];
        acc2[0] = fma2(ap, w0.u[0], acc2[0]);
        acc2[1] = fma2(ap, w0.u[1], acc2[1]);
        acc2[2] = fma2(ap, w1.u[0], acc2[2]);
        acc2[3] = fma2(ap, w1.u[1], acc2[3]);
    }
    unsigned long long dp = pack2(dn, dn);
    union { uint4 v; __half2 h2[4]; } o;
    #pragma unroll
    for (int q = 0; q < 4; q++)
        o.h2[q] = __float22half2_rn(unpack2(mul2(acc2[q], dp)));
    *(uint4*)(g_h2 + (size_t)n * D + c) = o.v;
}

// Final layer-2 aggregation (reads prescaled g_h2) -> fp32 output.
__global__ void agg2_kernel(const float* __restrict__ b2,
                            float* __restrict__ out) {
    int t = blockIdx.x * 256 + threadIdx.x;
    int n = t >> 3;
    if (n >= N_NODES) return;
    int c = (t & 7) * 8;

    float2 acc[4];
    aggregate8((const __half*)g_h2, n, c, acc);

    float dn = g_dinv[n];
    float4 b0 = *(const float4*)(b2 + c);
    float4 b1 = *(const float4*)(b2 + c + 4);
    float4 o0, o1;
    o0.x = fmaxf(fmaf(dn, acc[0].x, b0.x), 0.f);
    o0.y = fmaxf(fmaf(dn, acc[0].y, b0.y), 0.f);
    o0.z = fmaxf(fmaf(dn, acc[1].x, b0.z), 0.f);
    o0.w = fmaxf(fmaf(dn, acc[1].y, b0.w), 0.f);
    o1.x = fmaxf(fmaf(dn, acc[2].x, b1.x), 0.f);
    o1.y = fmaxf(fmaf(dn, acc[2].y, b1.y), 0.f);
    o1.z = fmaxf(fmaf(dn, acc[3].x, b1.z), 0.f);
    o1.w = fmaxf(fmaf(dn, acc[3].y, b1.w), 0.f);

    *(float4*)(out + (size_t)n * D + c)     = o0;
    *(float4*)(out + (size_t)n * D + c + 4) = o1;
}

// ---------------------------------------------------------------------------
extern "C" void kernel_launch(void* const* d_in, const int* in_sizes, int n_in,
                              void* d_out, int out_size) {
    const float* x  = (const float*)d_in[0];
    const int*   ei = (const int*)d_in[1];     // int32 edge_index (2, E) flattened
    const float* W1 = (const float*)d_in[2];
    const float* b1 = (const float*)d_in[3];
    const float* W2 = (const float*)d_in[4];
    const float* b2 = (const float*)d_in[5];
    float*       out = (float*)d_out;

    static cudaStream_t s1 = nullptr;
    static cudaEvent_t evOff = nullptr, evJoin = nullptr;
    if (!s1) {
        cudaStreamCreateWithFlags(&s1, cudaStreamNonBlocking);
        cudaEventCreateWithFlags(&evOff, cudaEventDisableTiming);
        cudaEventCreateWithFlags(&evJoin, cudaEventDisableTiming);
    }

    const int TB = 256;
    int nodeBlocks = (N_NODES + TB - 1) / TB;              // 391
    int deg4Blocks = (N_EDGES / 4 + TB - 1) / TB;          // 1563
    int bin2Blocks = (N_EDGES / 2 + TB - 1) / TB;          // 3125
    int aggBlocks  = (N_NODES * 8 + TB - 1) / TB;          // 3125

    // graph build prefix (produces g_off, g_cnt=0, g_dinv)
    init_kernel<<<nodeBlocks, TB>>>();
    deg_kernel<<<deg4Blocks, TB>>>(ei);
    offsets_kernel<<<nodeBlocks, TB>>>();

    // fork: gemm1 (FMA-bound, needs dinv only) overlaps bin (L2-atomic-bound)
    cudaEventRecord(evOff, 0);
    cudaStreamWaitEvent(s1, evOff, 0);
    gemm1_kernel<<<nodeBlocks, TB, 0, s1>>>(x, W1);
    cudaEventRecord(evJoin, s1);

    bin_kernel<<<bin2Blocks, TB>>>(ei);

    // join, fused layer boundary, final aggregation
    cudaStreamWaitEvent(0, evJoin, 0);
    fused_agg_gemm_kernel<<<aggBlocks, TB>>>(b1, W2);
    agg2_kernel<<<aggBlocks, TB>>>(b2, out);
}

// round 9
// speedup vs baseline: 1.5340x; 1.5340x over previous
#include <cuda_runtime.h>
#include <cuda_fp16.h>
#include <cuda_bf16.h>
#include <cstdint>

#define N_NODES 100000
#define N_EDGES 1600000
#define D 64

// GEMM tiling: 256 rows/block, 256 threads, each thread = 8 rows x 8 cols.
#define GR 256                 // rows per block
#define SA_STRIDE 68           // padded fp32 row stride (16B aligned, conflict-free)
#define SMEM_GEMM ((GR * SA_STRIDE + D * D) * 4)   // 69632 + 16384 = 86016 B

// ---------------- static device scratch (no allocation allowed) -------------
__device__ int    g_deg[N_NODES];       // in-degree (without self loop)
__device__ float  g_dinv[N_NODES];      // rsqrt(deg+1)
__device__ int    g_off[N_NODES];       // compact CSR offsets
__device__ int    g_cnt[N_NODES];       // fill cursors
__device__ int    g_src[N_EDGES];       // compact CSR-by-dst (6.4MB)
__device__ __half g_h[(size_t)N_NODES * D];   // layer-1 prescaled features (fp16)
__device__ __half g_h2[(size_t)N_NODES * D];  // layer-2 prescaled features (fp16)
__device__ float  g_t[(size_t)N_NODES * D];   // layer-1 activations (fp32)
__device__ int    g_cursor;

// ---------------- f32x2 packed-math helpers (Blackwell) ---------------------
__device__ __forceinline__ unsigned long long pack2(float lo, float hi) {
    unsigned long long r;
    asm("mov.b64 %0, {%1, %2};" : "=l"(r)
        : "r"(__float_as_uint(lo)), "r"(__float_as_uint(hi)));
    return r;
}
__device__ __forceinline__ unsigned long long fma2(unsigned long long a,
                                                   unsigned long long b,
                                                   unsigned long long c) {
    unsigned long long d;
    asm("fma.rn.f32x2 %0, %1, %2, %3;" : "=l"(d) : "l"(a), "l"(b), "l"(c));
    return d;
}
__device__ __forceinline__ unsigned long long mul2(unsigned long long a,
                                                   unsigned long long b) {
    unsigned long long d;
    asm("mul.rn.f32x2 %0, %1, %2;" : "=l"(d) : "l"(a), "l"(b));
    return d;
}
__device__ __forceinline__ float2 unpack2(unsigned long long v) {
    float2 f;
    unsigned lo, hi;
    asm("mov.b64 {%0, %1}, %2;" : "=r"(lo), "=r"(hi) : "l"(v));
    f.x = __uint_as_float(lo); f.y = __uint_as_float(hi);
    return f;
}

// ---------------------------------------------------------------------------
__global__ void init_kernel() {
    int i = blockIdx.x * blockDim.x + threadIdx.x;
    if (i == 0) g_cursor = 0;
    if (i < N_NODES) g_deg[i] = 0;
}

__global__ void deg_kernel(const int* __restrict__ ei) {
    int e4 = blockIdx.x * blockDim.x + threadIdx.x;
    if (e4 * 4 < N_EDGES) {
        int4 d4 = *(const int4*)(ei + N_EDGES + e4 * 4);
        atomicAdd(&g_deg[d4.x], 1);
        atomicAdd(&g_deg[d4.y], 1);
        atomicAdd(&g_deg[d4.z], 1);
        atomicAdd(&g_deg[d4.w], 1);
    }
}

__global__ void offsets_kernel() {
    int n = blockIdx.x * blockDim.x + threadIdx.x;
    int d = (n < N_NODES) ? g_deg[n] : 0;
    int lane = threadIdx.x & 31;
    int incl = d;
    #pragma unroll
    for (int o = 1; o < 32; o <<= 1) {
        int v = __shfl_up_sync(0xFFFFFFFFu, incl, o);
        if (lane >= o) incl += v;
    }
    int total = __shfl_sync(0xFFFFFFFFu, incl, 31);
    int base = 0;
    if (lane == 31) base = atomicAdd(&g_cursor, total);
    base = __shfl_sync(0xFFFFFFFFu, base, 31);
    if (n < N_NODES) {
        g_off[n]  = base + (incl - d);
        g_cnt[n]  = 0;
        g_dinv[n] = rsqrtf((float)(d + 1));
    }
}

__global__ void bin_kernel(const int* __restrict__ ei) {
    int e2 = blockIdx.x * blockDim.x + threadIdx.x;
    if (e2 * 2 < N_EDGES) {
        int2 s2 = *(const int2*)(ei + e2 * 2);
        int2 d2 = *(const int2*)(ei + N_EDGES + e2 * 2);
        int p0 = g_off[d2.x] + atomicAdd(&g_cnt[d2.x], 1);
        g_src[p0] = s2.x;
        int p1 = g_off[d2.y] + atomicAdd(&g_cnt[d2.y], 1);
        g_src[p1] = s2.y;
    }
}

// Row-blocked GEMM: out16[row] = half( dinv[row] * (A[row] @ W) ).
// 256 rows/block; thread (cg = t&7, ro = t>>3) computes rows ro*8..+7, cols cg*8..+7.
// W chunk (32B) loaded once per k serves 8 rows -> smem-traffic ~2B/FMA2.
__global__ __launch_bounds__(256, 2)
void gemm_kernel(const float* __restrict__ Ain,   // used if use_gt==0
                 const float* __restrict__ W,
                 int use_gt,                       // 1: A = g_t
                 int out_sel)                      // 0: g_h   1: g_h2
{
    extern __shared__ float smem[];
    float*  sA = smem;                         // [GR][SA_STRIDE]
    float4* sW = (float4*)(smem + GR * SA_STRIDE);  // [64][16]

    int t = threadIdx.x;
    const float* A = use_gt ? (const float*)g_t : Ain;
    int rowBase = blockIdx.x * GR;

    // stage W (1024 float4)
    const float4* Wv = (const float4*)W;
    #pragma unroll
    for (int r = 0; r < 4; r++) sW[t + 256 * r] = Wv[t + 256 * r];

    // stage A tile: idx = t + 256*i ; row = idx>>4 ; c4 = idx&15 (coalesced)
    #pragma unroll
    for (int i = 0; i < 16; i++) {
        int idx = t + 256 * i;
        int row = idx >> 4, c4 = idx & 15;
        int rg = rowBase + row;
        float4 v = (rg < N_NODES) ? ((const float4*)(A + (size_t)rg * D))[c4]
                                  : make_float4(0.f, 0.f, 0.f, 0.f);
        float* p = &sA[row * SA_STRIDE + c4 * 4];
        p[0] = v.x; p[1] = v.y; p[2] = v.z; p[3] = v.w;
    }
    __syncthreads();

    int cg  = t & 7;
    int ro8 = (t >> 3) * 8;

    unsigned long long acc[8][4];
    #pragma unroll
    for (int r = 0; r < 8; r++)
        #pragma unroll
        for (int j = 0; j < 4; j++) acc[r][j] = 0ull;

    #pragma unroll 4
    for (int k4 = 0; k4 < 16; k4++) {
        float4 a4[8];
        #pragma unroll
        for (int r = 0; r < 8; r++)
            a4[r] = *(const float4*)&sA[(ro8 + r) * SA_STRIDE + k4 * 4];
        #pragma unroll
        for (int kj = 0; kj < 4; kj++) {
            int k = k4 * 4 + kj;
            union { float4 f; unsigned long long u[2]; } w0, w1;
            w0.f = sW[k * 16 + cg * 2];
            w1.f = sW[k * 16 + cg * 2 + 1];
            #pragma unroll
            for (int r = 0; r < 8; r++) {
                float a = ((const float*)&a4[r])[kj];
                unsigned long long ap = pack2(a, a);
                acc[r][0] = fma2(ap, w0.u[0], acc[r][0]);
                acc[r][1] = fma2(ap, w0.u[1], acc[r][1]);
                acc[r][2] = fma2(ap, w1.u[0], acc[r][2]);
                acc[r][3] = fma2(ap, w1.u[1], acc[r][3]);
            }
        }
    }

    __half* outp = out_sel ? (__half*)g_h2 : (__half*)g_h;
    #pragma unroll
    for (int r = 0; r < 8; r++) {
        int rg = rowBase + ro8 + r;
        if (rg >= N_NODES) break;
        float dinv = g_dinv[rg];
        unsigned long long dp = pack2(dinv, dinv);
        union { uint4 v; __half2 h2[4]; } o;
        #pragma unroll
        for (int q = 0; q < 4; q++)
            o.h2[q] = __float22half2_rn(unpack2(mul2(acc[r][q], dp)));
        *(uint4*)(outp + (size_t)rg * D + cg * 8) = o.v;
    }
}

// Aggregate 8 columns of node n from prescaled fp16 buffer: acc = hs_n + sum hs_src.
__device__ __forceinline__ void aggregate8(const __half* __restrict__ hs,
                                           int n, int c, float2 acc[4]) {
    union { uint4 v; __half2 h2[4]; } u;
    u.v = *(const uint4*)(hs + (size_t)n * D + c);       // self term (prescaled)
    #pragma unroll
    for (int j = 0; j < 4; j++) acc[j] = __half22float2(u.h2[j]);

    int s0  = g_off[n];
    int cnt = g_deg[n];
    const int* lst = g_src + s0;
    #pragma unroll 4
    for (int i = 0; i < cnt; i++) {
        int s = lst[i];
        union { uint4 v; __half2 h2[4]; } w;
        w.v = *(const uint4*)(hs + (size_t)s * D + c);   // 128B row gather
        #pragma unroll
        for (int j = 0; j < 4; j++) {
            float2 f = __half22float2(w.h2[j]);
            acc[j].x += f.x; acc[j].y += f.y;
        }
    }
}

// out[n] = relu( dinv[n] * (hs_n + sum hs_src) + b ).  8 thr/node.
// sel==1: read g_h, write g_t (fp32).  sel==0: read g_h2, write out_ext.
__global__ void agg_kernel(const float* __restrict__ bias,
                           float* __restrict__ out_ext,
                           int sel)
{
    int t = blockIdx.x * 256 + threadIdx.x;
    int n = t >> 3;
    if (n >= N_NODES) return;
    int c = (t & 7) * 8;

    const __half* hs = sel ? (const __half*)g_h : (const __half*)g_h2;
    float2 acc[4];
    aggregate8(hs, n, c, acc);

    float dn = g_dinv[n];
    float4 b0 = *(const float4*)(bias + c);
    float4 b1 = *(const float4*)(bias + c + 4);
    float4 o0, o1;
    o0.x = fmaxf(fmaf(dn, acc[0].x, b0.x), 0.f);
    o0.y = fmaxf(fmaf(dn, acc[0].y, b0.y), 0.f);
    o0.z = fmaxf(fmaf(dn, acc[1].x, b0.z), 0.f);
    o0.w = fmaxf(fmaf(dn, acc[1].y, b0.w), 0.f);
    o1.x = fmaxf(fmaf(dn, acc[2].x, b1.x), 0.f);
    o1.y = fmaxf(fmaf(dn, acc[2].y, b1.y), 0.f);
    o1.z = fmaxf(fmaf(dn, acc[3].x, b1.z), 0.f);
    o1.w = fmaxf(fmaf(dn, acc[3].y, b1.w), 0.f);

    float* out = sel ? (float*)g_t : out_ext;
    *(float4*)(out + (size_t)n * D + c)     = o0;
    *(float4*)(out + (size_t)n * D + c + 4) = o1;
}

// ---------------------------------------------------------------------------
extern "C" void kernel_launch(void* const* d_in, const int* in_sizes, int n_in,
                              void* d_out, int out_size) {
    const float* x  = (const float*)d_in[0];
    const int*   ei = (const int*)d_in[1];     // int32 edge_index (2, E) flattened
    const float* W1 = (const float*)d_in[2];
    const float* b1 = (const float*)d_in[3];
    const float* W2 = (const float*)d_in[4];
    const float* b2 = (const float*)d_in[5];
    float*       out = (float*)d_out;

    static cudaStream_t s1 = nullptr;
    static cudaEvent_t evOff = nullptr, evJoin = nullptr;
    if (!s1) {
        cudaStreamCreateWithFlags(&s1, cudaStreamNonBlocking);
        cudaEventCreateWithFlags(&evOff, cudaEventDisableTiming);
        cudaEventCreateWithFlags(&evJoin, cudaEventDisableTiming);
        cudaFuncSetAttribute(gemm_kernel,
                             cudaFuncAttributeMaxDynamicSharedMemorySize,
                             SMEM_GEMM);
    }

    const int TB = 256;
    int nodeBlocks = (N_NODES + TB - 1) / TB;              // 391
    int deg4Blocks = (N_EDGES / 4 + TB - 1) / TB;          // 1563
    int bin2Blocks = (N_EDGES / 2 + TB - 1) / TB;          // 3125
    int aggBlocks  = (N_NODES * 8 + TB - 1) / TB;          // 3125
    int gemmBlocks = (N_NODES + GR - 1) / GR;              // 391

    // graph build prefix (produces g_off, g_cnt=0, g_dinv)
    init_kernel<<<nodeBlocks, TB>>>();
    deg_kernel<<<deg4Blocks, TB>>>(ei);
    offsets_kernel<<<nodeBlocks, TB>>>();

    // fork: gemm1 (fma/smem-bound, needs dinv only) overlaps bin (L2-atomic-bound)
    cudaEventRecord(evOff, 0);
    cudaStreamWaitEvent(s1, evOff, 0);
    gemm_kernel<<<gemmBlocks, TB, SMEM_GEMM, s1>>>(x, W1, 0, 0);   // x@W1 -> g_h
    cudaEventRecord(evJoin, s1);

    bin_kernel<<<bin2Blocks, TB>>>(ei);

    cudaStreamWaitEvent(0, evJoin, 0);
    agg_kernel<<<aggBlocks, TB>>>(b1, nullptr, 1);                 // g_h  -> g_t
    gemm_kernel<<<gemmBlocks, TB, SMEM_GEMM>>>(nullptr, W2, 1, 1); // g_t@W2 -> g_h2
    agg_kernel<<<aggBlocks, TB>>>(b2, out, 0);                     // g_h2 -> out
}